// round 3
// baseline (speedup 1.0000x reference)
#include <cuda_runtime.h>
#include <cstdint>
#include <math_constants.h>

// ---------------------------------------------------------------------------
// Paged-cache block-diagonal causal attention (fill chunk), fused flash-attn.
// TF32 mma.sync path, fp32 I/O.  R3: no P smem (shuffle fragment convert),
// conflict-free V stride, 2 CTAs/SM, MUFU exp2.
// ---------------------------------------------------------------------------

namespace {
constexpr int kNSeqs   = 8;
constexpr int kQLen    = 256;
constexpr int kKvLen   = 2048;
constexpr int kHeads   = 16;
constexpr int kHeadDim = 128;
constexpr int kCtxOld  = kKvLen - kQLen;    // 1792
constexpr int kOutCols = kHeads * kHeadDim; // 2048

constexpr int BM = 64;
constexpr int BN = 64;
constexpr int kThreads = 128;  // 4 warps, 16 query rows each

constexpr int KST = 132;  // Q/K smem stride (== 4 mod 32)
constexpr int VST = 136;  // V   smem stride (== 8 mod 32)

constexpr float kScaleLog2e = 0.08838834764831845f * 1.4426950408889634f;

constexpr int kQsOff = 0;
constexpr int kKsOff = kQsOff + BM * KST;
constexpr int kVsOff = kKsOff + BN * KST;
constexpr int kSmemFloats = kVsOff + BN * VST;  // 25600 floats = 102400 B
}  // namespace

__device__ __forceinline__ uint32_t f2tf32(float f) {
    uint32_t u;
    asm("cvt.rna.tf32.f32 %0, %1;" : "=r"(u) : "f"(f));
    return u;
}

__device__ __forceinline__ float fast_exp2(float x) {
    float r;
    asm("ex2.approx.ftz.f32 %0, %1;" : "=f"(r) : "f"(x));
    return r;
}

__device__ __forceinline__ void mma_tf32(float c[4], const uint32_t a[4],
                                         const uint32_t b[2]) {
    asm volatile(
        "mma.sync.aligned.m16n8k8.row.col.f32.tf32.tf32.f32 "
        "{%0,%1,%2,%3}, {%4,%5,%6,%7}, {%8,%9}, {%0,%1,%2,%3};"
        : "+f"(c[0]), "+f"(c[1]), "+f"(c[2]), "+f"(c[3])
        : "r"(a[0]), "r"(a[1]), "r"(a[2]), "r"(a[3]), "r"(b[0]), "r"(b[1]));
}

__global__ void __launch_bounds__(kThreads, 2)
fa_paged_kernel(const float* __restrict__ q, const float* __restrict__ kk,
                const float* __restrict__ vv, const float* __restrict__ k_cache,
                const float* __restrict__ v_cache,
                const int* __restrict__ ctx32, float* __restrict__ out) {
    extern __shared__ float smem[];
    float* Qs = smem + kQsOff;
    float* Ks = smem + kKsOff;
    float* Vs = smem + kVsOff;

    const int qt = blockIdx.x;   // 0..3
    const int h  = blockIdx.y;   // 0..15
    const int s  = blockIdx.z;   // 0..7
    const int q0 = qt * BM;

    const int tid  = threadIdx.x;
    const int warp = tid >> 5;
    const int lane = tid & 31;
    const int g = lane >> 2;
    const int t = lane & 3;

    // dtype probe: genuine int64 LE -> odd words 1,3,5 are all-zero high words.
    const bool ctx_is64 =
        (ctx32[1] == 0) && (ctx32[3] == 0) && (ctx32[5] == 0);

    // ---- load Q tile (pre-scaled, tf32-rounded) ----
    {
        const int r     = tid >> 1;
        const int cbase = (tid & 1) * 64;
        const float* src =
            q + ((size_t)(s * kQLen + q0 + r) * kHeads + h) * kHeadDim;
        uint32_t* dst = (uint32_t*)(Qs + r * KST);
#pragma unroll
        for (int i = 0; i < 16; i++) {
            float4 f = *(const float4*)(src + cbase + i * 4);
            dst[cbase + i * 4 + 0] = f2tf32(f.x * kScaleLog2e);
            dst[cbase + i * 4 + 1] = f2tf32(f.y * kScaleLog2e);
            dst[cbase + i * 4 + 2] = f2tf32(f.z * kScaleLog2e);
            dst[cbase + i * 4 + 3] = f2tf32(f.w * kScaleLog2e);
        }
    }

    float oacc[16][4];
#pragma unroll
    for (int nb = 0; nb < 16; nb++)
        oacc[nb][0] = oacc[nb][1] = oacc[nb][2] = oacc[nb][3] = 0.f;
    float m1 = -CUDART_INF_F, m2 = -CUDART_INF_F;
    float l1 = 0.f, l2 = 0.f;

    const int qr0 = warp * 16;
    const int n_kv = min(kKvLen, q0 + BM - 1 + kCtxOld + 1);
    const int n_tiles = n_kv / BN;

    const uint32_t* Qsu = (const uint32_t*)Qs;
    const uint32_t* Ksu = (const uint32_t*)Ks;
    const uint32_t* Vsu = (const uint32_t*)Vs;

    for (int tile = 0; tile < n_tiles; tile++) {
        const int j0 = tile * BN;
        __syncthreads();

        // ---- gather K/V tile into smem ----
        {
            const int jr    = tid >> 1;
            const int cbase = (tid & 1) * 64;
            const int j     = j0 + jr;
            const float *ksrc, *vsrc;
            if (j < kCtxOld) {
                const size_t ci = (size_t)s * kKvLen + j;
                const int slot = ctx_is64 ? ctx32[2 * ci] : ctx32[ci];
                const size_t base = ((size_t)slot * kHeads + h) * kHeadDim;
                ksrc = k_cache + base;
                vsrc = v_cache + base;
            } else {
                const size_t base =
                    ((size_t)(s * kQLen + (j - kCtxOld)) * kHeads + h) * kHeadDim;
                ksrc = kk + base;
                vsrc = vv + base;
            }
            uint32_t* kd = (uint32_t*)(Ks + jr * KST);
            uint32_t* vd = (uint32_t*)(Vs + jr * VST);
#pragma unroll
            for (int i = 0; i < 16; i++) {
                float4 kf = *(const float4*)(ksrc + cbase + i * 4);
                float4 vf = *(const float4*)(vsrc + cbase + i * 4);
                kd[cbase + i * 4 + 0] = f2tf32(kf.x);
                kd[cbase + i * 4 + 1] = f2tf32(kf.y);
                kd[cbase + i * 4 + 2] = f2tf32(kf.z);
                kd[cbase + i * 4 + 3] = f2tf32(kf.w);
                vd[cbase + i * 4 + 0] = f2tf32(vf.x);
                vd[cbase + i * 4 + 1] = f2tf32(vf.y);
                vd[cbase + i * 4 + 2] = f2tf32(vf.z);
                vd[cbase + i * 4 + 3] = f2tf32(vf.w);
            }
        }
        __syncthreads();

        // ---- S = Q * K^T ----
        float sacc[8][4];
#pragma unroll
        for (int nb = 0; nb < 8; nb++)
            sacc[nb][0] = sacc[nb][1] = sacc[nb][2] = sacc[nb][3] = 0.f;

#pragma unroll
        for (int kb = 0; kb < 16; kb++) {
            uint32_t a[4];
            const uint32_t* qrow = Qsu + (qr0 + g) * KST + kb * 8;
            a[0] = qrow[t];
            a[1] = qrow[8 * KST + t];
            a[2] = qrow[t + 4];
            a[3] = qrow[8 * KST + t + 4];
#pragma unroll
            for (int nb = 0; nb < 8; nb++) {
                uint32_t b[2];
                const uint32_t* krow = Ksu + (nb * 8 + g) * KST + kb * 8;
                b[0] = krow[t];
                b[1] = krow[t + 4];
                mma_tf32(sacc[nb], a, b);
            }
        }

        // ---- mask (single boundary tile only) ----
        if (j0 + BN - 1 > q0 + kCtxOld) {
            const int lim1 = q0 + qr0 + g + kCtxOld;
            const int lim2 = lim1 + 8;
#pragma unroll
            for (int nb = 0; nb < 8; nb++) {
                const int c0 = j0 + nb * 8 + 2 * t;
                const int c1 = c0 + 1;
                if (c0 > lim1) sacc[nb][0] = -1e30f;
                if (c1 > lim1) sacc[nb][1] = -1e30f;
                if (c0 > lim2) sacc[nb][2] = -1e30f;
                if (c1 > lim2) sacc[nb][3] = -1e30f;
            }
        }

        // ---- online softmax (exp2 domain); sacc becomes P in-place ----
        float mx1 = fmaxf(sacc[0][0], sacc[0][1]);
        float mx2 = fmaxf(sacc[0][2], sacc[0][3]);
#pragma unroll
        for (int nb = 1; nb < 8; nb++) {
            mx1 = fmaxf(mx1, fmaxf(sacc[nb][0], sacc[nb][1]));
            mx2 = fmaxf(mx2, fmaxf(sacc[nb][2], sacc[nb][3]));
        }
        mx1 = fmaxf(mx1, __shfl_xor_sync(0xffffffffu, mx1, 1));
        mx1 = fmaxf(mx1, __shfl_xor_sync(0xffffffffu, mx1, 2));
        mx2 = fmaxf(mx2, __shfl_xor_sync(0xffffffffu, mx2, 1));
        mx2 = fmaxf(mx2, __shfl_xor_sync(0xffffffffu, mx2, 2));

        const float m1n = fmaxf(m1, mx1);
        const float m2n = fmaxf(m2, mx2);
        const float al1 = fast_exp2(m1 - m1n);
        const float al2 = fast_exp2(m2 - m2n);
        m1 = m1n;
        m2 = m2n;

        float sum1 = 0.f, sum2 = 0.f;
#pragma unroll
        for (int nb = 0; nb < 8; nb++) {
            const float p0 = fast_exp2(sacc[nb][0] - m1);
            const float p1 = fast_exp2(sacc[nb][1] - m1);
            const float p2 = fast_exp2(sacc[nb][2] - m2);
            const float p3 = fast_exp2(sacc[nb][3] - m2);
            sum1 += p0 + p1;
            sum2 += p2 + p3;
            sacc[nb][0] = p0;
            sacc[nb][1] = p1;
            sacc[nb][2] = p2;
            sacc[nb][3] = p3;
        }
        sum1 += __shfl_xor_sync(0xffffffffu, sum1, 1);
        sum1 += __shfl_xor_sync(0xffffffffu, sum1, 2);
        sum2 += __shfl_xor_sync(0xffffffffu, sum2, 1);
        sum2 += __shfl_xor_sync(0xffffffffu, sum2, 2);
        l1 = l1 * al1 + sum1;
        l2 = l2 * al2 + sum2;

#pragma unroll
        for (int nb = 0; nb < 16; nb++) {
            oacc[nb][0] *= al1;
            oacc[nb][1] *= al1;
            oacc[nb][2] *= al2;
            oacc[nb][3] *= al2;
        }

        // ---- O += P * V ----
        // Convert P from accumulator layout (g,2t)/(g,2t+1) to A-operand
        // layout (g,t)/(g,t+4) via intra-quad shuffles (no smem round-trip).
        const int src1 = (lane & ~3) | (t >> 1);
        const int src2 = src1 + 2;
        const bool odd = (t & 1);
#pragma unroll
        for (int kb = 0; kb < 8; kb++) {
            const float y0 = __shfl_sync(0xffffffffu, sacc[kb][0], src1);
            const float y1 = __shfl_sync(0xffffffffu, sacc[kb][1], src1);
            const float y2 = __shfl_sync(0xffffffffu, sacc[kb][2], src1);
            const float y3 = __shfl_sync(0xffffffffu, sacc[kb][3], src1);
            const float z0 = __shfl_sync(0xffffffffu, sacc[kb][0], src2);
            const float z1 = __shfl_sync(0xffffffffu, sacc[kb][1], src2);
            const float z2 = __shfl_sync(0xffffffffu, sacc[kb][2], src2);
            const float z3 = __shfl_sync(0xffffffffu, sacc[kb][3], src2);
            uint32_t a[4];
            a[0] = f2tf32(odd ? y1 : y0);  // P(g,    t)
            a[1] = f2tf32(odd ? y3 : y2);  // P(g+8,  t)
            a[2] = f2tf32(odd ? z1 : z0);  // P(g,    t+4)
            a[3] = f2tf32(odd ? z3 : z2);  // P(g+8,  t+4)
#pragma unroll
            for (int nb = 0; nb < 16; nb++) {
                uint32_t b[2];
                const uint32_t* vrow = Vsu + (kb * 8 + t) * VST + nb * 8 + g;
                b[0] = vrow[0];
                b[1] = vrow[4 * VST];
                mma_tf32(oacc[nb], a, b);
            }
        }
    }

    // ---- epilogue ----
    const float inv1 = 1.f / l1;
    const float inv2 = 1.f / l2;
    const int row1 = s * kQLen + q0 + qr0 + g;
    float* o1 = out + (size_t)row1 * kOutCols + h * kHeadDim;
    float* o2 = o1 + (size_t)8 * kOutCols;
#pragma unroll
    for (int nb = 0; nb < 16; nb++) {
        const int c = nb * 8 + 2 * t;
        float2 w1 = make_float2(oacc[nb][0] * inv1, oacc[nb][1] * inv1);
        float2 w2 = make_float2(oacc[nb][2] * inv2, oacc[nb][3] * inv2);
        *(float2*)(o1 + c) = w1;
        *(float2*)(o2 + c) = w2;
    }
}

extern "C" void kernel_launch(void* const* d_in, const int* in_sizes, int n_in,
                              void* d_out, int out_size) {
    const float* q  = (const float*)d_in[0];
    const float* k  = (const float*)d_in[1];
    const float* v  = (const float*)d_in[2];
    const float* kc = (const float*)d_in[3];
    const float* vc = (const float*)d_in[4];
    const int* ctx = (const int*)d_in[6];
    float* out = (float*)d_out;

    const int smem_bytes = kSmemFloats * (int)sizeof(float);
    cudaFuncSetAttribute(fa_paged_kernel,
                         cudaFuncAttributeMaxDynamicSharedMemorySize, smem_bytes);
    dim3 grid(kQLen / BM, kHeads, kNSeqs);
    fa_paged_kernel<<<grid, kThreads, smem_bytes>>>(q, k, v, kc, vc, ctx, out);
}

// round 5
// speedup vs baseline: 1.6894x; 1.6894x over previous
#include <cuda_runtime.h>
#include <cuda_fp16.h>
#include <cstdint>
#include <math_constants.h>

// ---------------------------------------------------------------------------
// Paged-cache block-diagonal causal attention (fill chunk), fused flash-attn.
// FP16 mma.sync m16n8k16 (fp32 accum), fp32 I/O. Register-resident Q frags,
// transposed V tile, smem P round-trip, 2 CTAs/SM.
//
// kv j < 1792 -> cache[ctx32[s*2048+j]];  j >= 1792 -> new k/v row j-1792.
// Mask: kv j visible to query i iff j <= i + 1792.
// ---------------------------------------------------------------------------

namespace {
constexpr int kNSeqs   = 8;
constexpr int kQLen    = 256;
constexpr int kKvLen   = 2048;
constexpr int kHeads   = 16;
constexpr int kHeadDim = 128;
constexpr int kCtxOld  = 1792;
constexpr int kOutCols = 2048;

constexpr int BM = 64;
constexpr int BN = 64;
constexpr int kThreads = 128;  // 4 warps, 16 query rows each

// u32-unit smem strides (fp16 pairs). 68 == 4 (mod 32), 36 == 4 (mod 32):
// fragment access bank = 4g + t -> conflict-free.
constexpr int KST = 68;  // Q/K tiles: 64 u32 per row + 4 pad
constexpr int VST = 36;  // Vt / P tiles: 32 u32 per row + 4 pad

constexpr float kScaleLog2e = 0.08838834764831845f * 1.4426950408889634f;

// u32 offsets within smem
constexpr int kKOff  = 0;                    // K: 64*68  = 4352
constexpr int kQOff  = 4352;                 // Q: 64*68  = 4352 (prologue only)
constexpr int kVtOff = 4352;                 // Vt: 128*36 = 4608 (aliases Q)
constexpr int kPOff  = kVtOff + 128 * VST;   // P: 4*16*36 = 2304
constexpr int kSmemU32 = kPOff + 4 * 16 * VST;  // 11264 u32 = 45056 B
}  // namespace

__device__ __forceinline__ uint32_t pack2(float lo, float hi) {
    __half2 h = __floats2half2_rn(lo, hi);  // .x = lo (low half)
    return *reinterpret_cast<uint32_t*>(&h);
}

__device__ __forceinline__ float fast_exp2(float x) {
    float r;
    asm("ex2.approx.ftz.f32 %0, %1;" : "=f"(r) : "f"(x));
    return r;
}

__device__ __forceinline__ void mma_f16(float c[4], const uint32_t a[4],
                                        const uint32_t b[2]) {
    asm volatile(
        "mma.sync.aligned.m16n8k16.row.col.f32.f16.f16.f32 "
        "{%0,%1,%2,%3}, {%4,%5,%6,%7}, {%8,%9}, {%0,%1,%2,%3};"
        : "+f"(c[0]), "+f"(c[1]), "+f"(c[2]), "+f"(c[3])
        : "r"(a[0]), "r"(a[1]), "r"(a[2]), "r"(a[3]), "r"(b[0]), "r"(b[1]));
}

__global__ void __launch_bounds__(kThreads, 2)
fa_fp16_kernel(const float* __restrict__ q, const float* __restrict__ kk,
               const float* __restrict__ vv, const float* __restrict__ k_cache,
               const float* __restrict__ v_cache,
               const int* __restrict__ ctx32, float* __restrict__ out) {
    extern __shared__ uint32_t smem[];
    uint32_t* Ksu = smem + kKOff;
    uint32_t* Qsu = smem + kQOff;
    uint32_t* Vtu = smem + kVtOff;

    const int qt = blockIdx.x;   // 0..3
    const int h  = blockIdx.y;   // 0..15
    const int s  = blockIdx.z;   // 0..7
    const int q0 = qt * BM;

    const int tid  = threadIdx.x;
    const int warp = tid >> 5;
    const int lane = tid & 31;
    const int g = lane >> 2;     // row-in-8
    const int t = lane & 3;      // thread-in-quad

    uint32_t* Psu = smem + kPOff + warp * 16 * VST;

    // ctx dtype probe (int64 LE -> odd words 1,3,5 all zero)
    const bool ctx_is64 =
        (ctx32[1] == 0) && (ctx32[3] == 0) && (ctx32[5] == 0);

    // ---- prologue: Q tile -> smem (scaled, fp16), then frags -> registers ----
    {
        const int r = tid >> 1;
        const int hh = tid & 1;
        const float* src =
            q + ((size_t)(s * kQLen + q0 + r) * kHeads + h) * kHeadDim + hh * 64;
        uint32_t* dst = Qsu + r * KST + hh * 32;
#pragma unroll
        for (int i = 0; i < 16; i++) {
            float4 f = *(const float4*)(src + i * 4);
            uint2 u;
            u.x = pack2(f.x * kScaleLog2e, f.y * kScaleLog2e);
            u.y = pack2(f.z * kScaleLog2e, f.w * kScaleLog2e);
            *(uint2*)(dst + 2 * i) = u;
        }
    }
    __syncthreads();

    const int qr0 = warp * 16;
    uint32_t qf[8][4];  // Q fragments, register-resident (k = 128 -> 8 ksteps)
#pragma unroll
    for (int ks = 0; ks < 8; ks++) {
        const uint32_t* r0 = Qsu + (qr0 + g) * KST + ks * 8;
        const uint32_t* r1 = r0 + 8 * KST;
        qf[ks][0] = r0[t];
        qf[ks][1] = r1[t];
        qf[ks][2] = r0[t + 4];
        qf[ks][3] = r1[t + 4];
    }
    __syncthreads();  // Q reads done; Vt may overwrite the aliased region

    float oacc[16][4];
#pragma unroll
    for (int nb = 0; nb < 16; nb++)
        oacc[nb][0] = oacc[nb][1] = oacc[nb][2] = oacc[nb][3] = 0.f;
    float m1 = -CUDART_INF_F, m2 = -CUDART_INF_F;
    float l1 = 0.f, l2 = 0.f;

    const int n_tiles = (q0 + BM - 1 + kCtxOld + 1) / BN;  // 29..32

    for (int tile = 0; tile < n_tiles; tile++) {
        const int j0 = tile * BN;
        if (tile > 0) __syncthreads();  // previous tile's smem reads done

        // ---- gather K rows (each thread: half a row) ----
        {
            const int r  = tid >> 1;
            const int hh = tid & 1;
            const int j  = j0 + r;
            const float* ksrc;
            if (j < kCtxOld) {
                const size_t ci = (size_t)s * kKvLen + j;
                const int slot = ctx_is64 ? ctx32[2 * ci] : ctx32[ci];
                ksrc = k_cache + ((size_t)slot * kHeads + h) * kHeadDim;
            } else {
                ksrc = kk + ((size_t)(s * kQLen + (j - kCtxOld)) * kHeads + h) *
                                kHeadDim;
            }
            ksrc += hh * 64;
            uint32_t* dst = Ksu + r * KST + hh * 32;
#pragma unroll
            for (int i = 0; i < 16; i++) {
                float4 f = *(const float4*)(ksrc + i * 4);
                uint2 u;
                u.x = pack2(f.x, f.y);
                u.y = pack2(f.z, f.w);
                *(uint2*)(dst + 2 * i) = u;
            }
        }

        // ---- gather V rows transposed: Vt[d][j-pair] ----
        {
            const int p  = tid & 31;       // j-pair 0..31
            const int db = tid >> 5;       // d-block 0..3
            const int d0 = db * 32;
            const int j1 = j0 + 2 * p;
            const float *v1, *v2;
            if (j1 < kCtxOld) {
                const size_t ci = (size_t)s * kKvLen + j1;
                const int slot = ctx_is64 ? ctx32[2 * ci] : ctx32[ci];
                v1 = v_cache + ((size_t)slot * kHeads + h) * kHeadDim;
            } else {
                v1 = vv + ((size_t)(s * kQLen + (j1 - kCtxOld)) * kHeads + h) *
                              kHeadDim;
            }
            if (j1 + 1 < kCtxOld) {
                const size_t ci = (size_t)s * kKvLen + j1 + 1;
                const int slot = ctx_is64 ? ctx32[2 * ci] : ctx32[ci];
                v2 = v_cache + ((size_t)slot * kHeads + h) * kHeadDim;
            } else {
                v2 = vv + ((size_t)(s * kQLen + (j1 + 1 - kCtxOld)) * kHeads + h) *
                              kHeadDim;
            }
            v1 += d0;
            v2 += d0;
#pragma unroll
            for (int i = 0; i < 8; i++) {
                float4 a = *(const float4*)(v1 + i * 4);
                float4 b = *(const float4*)(v2 + i * 4);
                uint32_t* dst = Vtu + (d0 + 4 * i) * VST + p;
                dst[0 * VST] = pack2(a.x, b.x);
                dst[1 * VST] = pack2(a.y, b.y);
                dst[2 * VST] = pack2(a.z, b.z);
                dst[3 * VST] = pack2(a.w, b.w);
            }
        }
        __syncthreads();

        // ---- S = Q K^T  (8 ksteps of 16; Q frags in registers) ----
        float sacc[8][4];
#pragma unroll
        for (int nb = 0; nb < 8; nb++)
            sacc[nb][0] = sacc[nb][1] = sacc[nb][2] = sacc[nb][3] = 0.f;

#pragma unroll
        for (int ks = 0; ks < 8; ks++) {
#pragma unroll
            for (int nb = 0; nb < 8; nb++) {
                uint32_t b[2];
                const uint32_t* krow = Ksu + (nb * 8 + g) * KST + ks * 8;
                b[0] = krow[t];
                b[1] = krow[t + 4];
                mma_f16(sacc[nb], qf[ks], b);
            }
        }

        // ---- bottom-right causal mask (boundary tile only) ----
        if (j0 + BN - 1 > q0 + kCtxOld) {
            const int lim1 = q0 + qr0 + g + kCtxOld;
            const int lim2 = lim1 + 8;
#pragma unroll
            for (int nb = 0; nb < 8; nb++) {
                const int c0 = j0 + nb * 8 + 2 * t;
                const int c1 = c0 + 1;
                if (c0 > lim1) sacc[nb][0] = -1e30f;
                if (c1 > lim1) sacc[nb][1] = -1e30f;
                if (c0 > lim2) sacc[nb][2] = -1e30f;
                if (c1 > lim2) sacc[nb][3] = -1e30f;
            }
        }

        // ---- online softmax (exp2 domain) ----
        float mx1 = fmaxf(sacc[0][0], sacc[0][1]);
        float mx2 = fmaxf(sacc[0][2], sacc[0][3]);
#pragma unroll
        for (int nb = 1; nb < 8; nb++) {
            mx1 = fmaxf(mx1, fmaxf(sacc[nb][0], sacc[nb][1]));
            mx2 = fmaxf(mx2, fmaxf(sacc[nb][2], sacc[nb][3]));
        }
        mx1 = fmaxf(mx1, __shfl_xor_sync(0xffffffffu, mx1, 1));
        mx1 = fmaxf(mx1, __shfl_xor_sync(0xffffffffu, mx1, 2));
        mx2 = fmaxf(mx2, __shfl_xor_sync(0xffffffffu, mx2, 1));
        mx2 = fmaxf(mx2, __shfl_xor_sync(0xffffffffu, mx2, 2));

        const float m1n = fmaxf(m1, mx1);
        const float m2n = fmaxf(m2, mx2);
        const float al1 = fast_exp2(m1 - m1n);
        const float al2 = fast_exp2(m2 - m2n);
        m1 = m1n;
        m2 = m2n;

        float sum1 = 0.f, sum2 = 0.f;
#pragma unroll
        for (int nb = 0; nb < 8; nb++) {
            const float p0 = fast_exp2(sacc[nb][0] - m1);
            const float p1 = fast_exp2(sacc[nb][1] - m1);
            const float p2 = fast_exp2(sacc[nb][2] - m2);
            const float p3 = fast_exp2(sacc[nb][3] - m2);
            sum1 += p0 + p1;
            sum2 += p2 + p3;
            uint32_t* pr = Psu + g * VST + nb * 4 + t;
            pr[0] = pack2(p0, p1);
            pr[8 * VST] = pack2(p2, p3);
        }
        sum1 += __shfl_xor_sync(0xffffffffu, sum1, 1);
        sum1 += __shfl_xor_sync(0xffffffffu, sum1, 2);
        sum2 += __shfl_xor_sync(0xffffffffu, sum2, 1);
        sum2 += __shfl_xor_sync(0xffffffffu, sum2, 2);
        l1 = l1 * al1 + sum1;
        l2 = l2 * al2 + sum2;

#pragma unroll
        for (int nb = 0; nb < 16; nb++) {
            oacc[nb][0] *= al1;
            oacc[nb][1] *= al1;
            oacc[nb][2] *= al2;
            oacc[nb][3] *= al2;
        }
        __syncwarp();  // P visible within warp

        // ---- O += P V  (A = P smem, B = Vt smem) ----
#pragma unroll
        for (int ks = 0; ks < 4; ks++) {
            uint32_t a[4];
            const uint32_t* p0r = Psu + g * VST + ks * 8;
            const uint32_t* p1r = p0r + 8 * VST;
            a[0] = p0r[t];
            a[1] = p1r[t];
            a[2] = p0r[t + 4];
            a[3] = p1r[t + 4];
#pragma unroll
            for (int nb = 0; nb < 16; nb++) {
                uint32_t b[2];
                const uint32_t* vrow = Vtu + (nb * 8 + g) * VST + ks * 8;
                b[0] = vrow[t];
                b[1] = vrow[t + 4];
                mma_f16(oacc[nb], a, b);
            }
        }
    }

    // ---- epilogue: normalize and store ----
    const float inv1 = 1.f / l1;
    const float inv2 = 1.f / l2;
    const int row1 = s * kQLen + q0 + qr0 + g;
    float* o1 = out + (size_t)row1 * kOutCols + h * kHeadDim;
    float* o2 = o1 + (size_t)8 * kOutCols;
#pragma unroll
    for (int nb = 0; nb < 16; nb++) {
        const int c = nb * 8 + 2 * t;
        float2 w1 = make_float2(oacc[nb][0] * inv1, oacc[nb][1] * inv1);
        float2 w2 = make_float2(oacc[nb][2] * inv2, oacc[nb][3] * inv2);
        *(float2*)(o1 + c) = w1;
        *(float2*)(o2 + c) = w2;
    }
}

extern "C" void kernel_launch(void* const* d_in, const int* in_sizes, int n_in,
                              void* d_out, int out_size) {
    const float* q  = (const float*)d_in[0];
    const float* k  = (const float*)d_in[1];
    const float* v  = (const float*)d_in[2];
    const float* kc = (const float*)d_in[3];
    const float* vc = (const float*)d_in[4];
    const int* ctx = (const int*)d_in[6];
    float* out = (float*)d_out;

    const int smem_bytes = kSmemU32 * (int)sizeof(uint32_t);
    cudaFuncSetAttribute(fa_fp16_kernel,
                         cudaFuncAttributeMaxDynamicSharedMemorySize, smem_bytes);
    dim3 grid(kQLen / BM, kHeads, kNSeqs);
    fa_fp16_kernel<<<grid, kThreads, smem_bytes>>>(q, k, v, kc, vc, ctx, out);
}

// round 7
// speedup vs baseline: 2.5235x; 1.4937x over previous
#include <cuda_runtime.h>
#include <cuda_fp16.h>
#include <cstdint>
#include <math_constants.h>

// ---------------------------------------------------------------------------
// Paged-cache block-diagonal causal attention (fill chunk), fused flash-attn.
// FP16 mma.sync m16n8k16 (fp32 accum), fp32 I/O.
// R7: R6 with the gather swizzle chunk-index fix (4*pass, not 2*pass).
// Coalesced gather, ldmatrix(+.trans) feeding, XOR-swizzled smem, 2 CTAs/SM.
//
// kv j < 1792 -> cache[ctx32[s*2048+j]];  j >= 1792 -> new k/v row j-1792.
// Mask: kv j visible to query i iff j <= i + 1792.
// ---------------------------------------------------------------------------

namespace {
constexpr int kNSeqs   = 8;
constexpr int kQLen    = 256;
constexpr int kKvLen   = 2048;
constexpr int kHeads   = 16;
constexpr int kHeadDim = 128;
constexpr int kCtxOld  = 1792;
constexpr int kOutCols = 2048;

constexpr int BM = 64;
constexpr int BN = 64;
constexpr int kThreads = 128;  // 4 warps, 16 query rows each

constexpr float kScaleLog2e = 0.08838834764831845f * 1.4426950408889634f;

// u32 offsets. K/V tiles: 64 rows x 64 u32 (128 halfs), XOR-swizzled
// (16B chunk index ^ (row & 7)).  P: per warp 16 rows x 32 u32, swizzled.
// Q prologue aliases the V region.
constexpr int kKOff = 0;
constexpr int kVOff = 4096;
constexpr int kPOff = 8192;                  // + warp*512
constexpr int kSmemU32 = kPOff + 4 * 512;    // 10240 u32 = 40960 B
}  // namespace

__device__ __forceinline__ uint32_t smem_u32(const void* p) {
    uint32_t a;
    asm("{ .reg .u64 t; cvta.to.shared.u64 t, %1; cvt.u32.u64 %0, t; }"
        : "=r"(a) : "l"(p));
    return a;
}

__device__ __forceinline__ uint32_t pack2(float lo, float hi) {
    __half2 h = __floats2half2_rn(lo, hi);
    return *reinterpret_cast<uint32_t*>(&h);
}

__device__ __forceinline__ float fast_exp2(float x) {
    float r;
    asm("ex2.approx.ftz.f32 %0, %1;" : "=f"(r) : "f"(x));
    return r;
}

__device__ __forceinline__ void mma_f16(float c[4], const uint32_t a[4],
                                        const uint32_t* b) {
    asm volatile(
        "mma.sync.aligned.m16n8k16.row.col.f32.f16.f16.f32 "
        "{%0,%1,%2,%3}, {%4,%5,%6,%7}, {%8,%9}, {%0,%1,%2,%3};"
        : "+f"(c[0]), "+f"(c[1]), "+f"(c[2]), "+f"(c[3])
        : "r"(a[0]), "r"(a[1]), "r"(a[2]), "r"(a[3]), "r"(b[0]), "r"(b[1]));
}

__device__ __forceinline__ void ldm_x4(uint32_t r[4], uint32_t addr) {
    asm volatile(
        "ldmatrix.sync.aligned.m8n8.x4.shared.b16 {%0,%1,%2,%3}, [%4];"
        : "=r"(r[0]), "=r"(r[1]), "=r"(r[2]), "=r"(r[3]) : "r"(addr));
}

__device__ __forceinline__ void ldm_x4_t(uint32_t r[4], uint32_t addr) {
    asm volatile(
        "ldmatrix.sync.aligned.m8n8.x4.trans.shared.b16 {%0,%1,%2,%3}, [%4];"
        : "=r"(r[0]), "=r"(r[1]), "=r"(r[2]), "=r"(r[3]) : "r"(addr));
}

__global__ void __launch_bounds__(kThreads, 2)
fa_fp16_kernel(const float* __restrict__ q, const float* __restrict__ kk,
               const float* __restrict__ vv, const float* __restrict__ k_cache,
               const float* __restrict__ v_cache,
               const int* __restrict__ ctx32, float* __restrict__ out) {
    extern __shared__ uint32_t smem[];
    const uint32_t sb = smem_u32(smem);

    const int qt = blockIdx.x;   // 0..3
    const int h  = blockIdx.y;   // 0..15
    const int s  = blockIdx.z;   // 0..7
    const int q0 = qt * BM;

    const int tid  = threadIdx.x;
    const int warp = tid >> 5;
    const int lane = tid & 31;
    const int g = lane >> 2;
    const int t = lane & 3;

    // ctx dtype probe (int64 LE -> odd words 1,3,5 all zero)
    const bool ctx_is64 =
        (ctx32[1] == 0) && (ctx32[3] == 0) && (ctx32[5] == 0);

    // ---- prologue: Q -> smem (V region, plain stride 64), frags -> regs ----
    {
        const int r = tid >> 1;
        const int hh = tid & 1;
        const float* src =
            q + ((size_t)(s * kQLen + q0 + r) * kHeads + h) * kHeadDim + hh * 64;
        uint32_t* dst = smem + kVOff + r * 64 + hh * 32;
#pragma unroll
        for (int i = 0; i < 16; i++) {
            float4 f = *(const float4*)(src + i * 4);
            uint2 u;
            u.x = pack2(f.x * kScaleLog2e, f.y * kScaleLog2e);
            u.y = pack2(f.z * kScaleLog2e, f.w * kScaleLog2e);
            *(uint2*)(dst + 2 * i) = u;
        }
    }
    __syncthreads();

    const int qr0 = warp * 16;
    uint32_t qf[8][4];
#pragma unroll
    for (int ks = 0; ks < 8; ks++) {
        const uint32_t* r0 = smem + kVOff + (qr0 + g) * 64 + ks * 8;
        qf[ks][0] = r0[t];
        qf[ks][1] = r0[8 * 64 + t];
        qf[ks][2] = r0[t + 4];
        qf[ks][3] = r0[8 * 64 + t + 4];
    }
    __syncthreads();  // Q reads done; V gather may overwrite

    float oacc[16][4];
#pragma unroll
    for (int nb = 0; nb < 16; nb++)
        oacc[nb][0] = oacc[nb][1] = oacc[nb][2] = oacc[nb][3] = 0.f;
    float m1 = -CUDART_INF_F, m2 = -CUDART_INF_F;
    float l1 = 0.f, l2 = 0.f;

    const int n_tiles = (q0 + BM - 1 + kCtxOld + 1) / BN;  // 29..32

    const int rseg = lane >> 3;  // gather: row within group of 4
    const int c    = lane & 7;   // gather: 16B fp32 chunk within 128B pass

    for (int tile = 0; tile < n_tiles; tile++) {
        const int j0 = tile * BN;
        if (tile > 0) __syncthreads();

        // ---- gather K,V rows (coalesced: 8 threads x 16B per row-pass) ----
#pragma unroll
        for (int rg = 0; rg < 4; rg++) {
            const int row = warp * 16 + rg * 4 + rseg;
            const int j = j0 + row;
            const float *ksrc, *vsrc;
            if (j < kCtxOld) {
                const size_t ci = (size_t)s * kKvLen + j;
                const int slot = ctx_is64 ? ctx32[2 * ci] : ctx32[ci];
                const size_t base = ((size_t)slot * kHeads + h) * kHeadDim;
                ksrc = k_cache + base;
                vsrc = v_cache + base;
            } else {
                const size_t base =
                    ((size_t)(s * kQLen + (j - kCtxOld)) * kHeads + h) * kHeadDim;
                ksrc = kk + base;
                vsrc = vv + base;
            }
            const int xr = row & 7;
            uint32_t* kd = smem + kKOff + row * 64;
            uint32_t* vd = smem + kVOff + row * 64;
#pragma unroll
            for (int pass = 0; pass < 4; pass++) {
                // thread covers halfs [pass*32 + c*4, +4) -> 16B chunk
                // index 4*pass + (c>>1), u32 offset (c&1)*2 within chunk.
                const int col =
                    (((4 * pass + (c >> 1)) ^ xr) << 2) + (c & 1) * 2;
                float4 kf = *(const float4*)(ksrc + pass * 32 + c * 4);
                uint2 ku;
                ku.x = pack2(kf.x, kf.y);
                ku.y = pack2(kf.z, kf.w);
                *(uint2*)(kd + col) = ku;
                float4 vf = *(const float4*)(vsrc + pass * 32 + c * 4);
                uint2 vu;
                vu.x = pack2(vf.x, vf.y);
                vu.y = pack2(vf.z, vf.w);
                *(uint2*)(vd + col) = vu;
            }
        }
        __syncthreads();

        // ---- S = Q K^T  (b-frags via ldmatrix.x4, 2 nb per instr) ----
        float sacc[8][4];
#pragma unroll
        for (int nb = 0; nb < 8; nb++)
            sacc[nb][0] = sacc[nb][1] = sacc[nb][2] = sacc[nb][3] = 0.f;

        const int m_id = lane >> 3;   // matrix index within x4
        const int lr   = lane & 7;    // row within matrix
#pragma unroll
        for (int ks = 0; ks < 8; ks++) {
#pragma unroll
            for (int nbp = 0; nbp < 4; nbp++) {
                const int row_n = nbp * 16 + (m_id >> 1) * 8 + lr;
                const uint32_t addr =
                    sb + (uint32_t)(kKOff + row_n * 64 +
                                    (((ks * 2 + (m_id & 1)) ^ (row_n & 7)) << 2)) * 4;
                uint32_t b4[4];
                ldm_x4(b4, addr);
                mma_f16(sacc[2 * nbp], qf[ks], b4);
                mma_f16(sacc[2 * nbp + 1], qf[ks], b4 + 2);
            }
        }

        // ---- bottom-right causal mask (boundary tile only) ----
        if (j0 + BN - 1 > q0 + kCtxOld) {
            const int lim1 = q0 + qr0 + g + kCtxOld;
            const int lim2 = lim1 + 8;
#pragma unroll
            for (int nb = 0; nb < 8; nb++) {
                const int c0 = j0 + nb * 8 + 2 * t;
                const int c1 = c0 + 1;
                if (c0 > lim1) sacc[nb][0] = -1e30f;
                if (c1 > lim1) sacc[nb][1] = -1e30f;
                if (c0 > lim2) sacc[nb][2] = -1e30f;
                if (c1 > lim2) sacc[nb][3] = -1e30f;
            }
        }

        // ---- online softmax (exp2 domain) ----
        float mx1 = fmaxf(sacc[0][0], sacc[0][1]);
        float mx2 = fmaxf(sacc[0][2], sacc[0][3]);
#pragma unroll
        for (int nb = 1; nb < 8; nb++) {
            mx1 = fmaxf(mx1, fmaxf(sacc[nb][0], sacc[nb][1]));
            mx2 = fmaxf(mx2, fmaxf(sacc[nb][2], sacc[nb][3]));
        }
        mx1 = fmaxf(mx1, __shfl_xor_sync(0xffffffffu, mx1, 1));
        mx1 = fmaxf(mx1, __shfl_xor_sync(0xffffffffu, mx1, 2));
        mx2 = fmaxf(mx2, __shfl_xor_sync(0xffffffffu, mx2, 1));
        mx2 = fmaxf(mx2, __shfl_xor_sync(0xffffffffu, mx2, 2));

        const float m1n = fmaxf(m1, mx1);
        const float m2n = fmaxf(m2, mx2);
        const float al1 = fast_exp2(m1 - m1n);
        const float al2 = fast_exp2(m2 - m2n);
        m1 = m1n;
        m2 = m2n;

        float sum1 = 0.f, sum2 = 0.f;
        uint32_t* Pw = smem + kPOff + warp * 512;
#pragma unroll
        for (int nb = 0; nb < 8; nb++) {
            const float p0 = fast_exp2(sacc[nb][0] - m1);
            const float p1 = fast_exp2(sacc[nb][1] - m1);
            const float p2 = fast_exp2(sacc[nb][2] - m2);
            const float p3 = fast_exp2(sacc[nb][3] - m2);
            sum1 += p0 + p1;
            sum2 += p2 + p3;
            uint32_t* pr = Pw + g * 32 + ((nb ^ g) << 2) + t;
            pr[0] = pack2(p0, p1);
            pr[8 * 32] = pack2(p2, p3);
        }
        sum1 += __shfl_xor_sync(0xffffffffu, sum1, 1);
        sum1 += __shfl_xor_sync(0xffffffffu, sum1, 2);
        sum2 += __shfl_xor_sync(0xffffffffu, sum2, 1);
        sum2 += __shfl_xor_sync(0xffffffffu, sum2, 2);
        l1 = l1 * al1 + sum1;
        l2 = l2 * al2 + sum2;

#pragma unroll
        for (int nb = 0; nb < 16; nb++) {
            oacc[nb][0] *= al1;
            oacc[nb][1] *= al1;
            oacc[nb][2] *= al2;
            oacc[nb][3] *= al2;
        }
        __syncwarp();  // P visible within warp

        // ---- O += P V  (a via ldmatrix, b via ldmatrix.trans) ----
#pragma unroll
        for (int ks = 0; ks < 4; ks++) {
            uint32_t a[4];
            {
                const int rowp = lane & 15;
                const uint32_t addr =
                    sb + (uint32_t)(kPOff + warp * 512 + rowp * 32 +
                                    (((ks * 2 + (lane >> 4)) ^ (rowp & 7)) << 2)) * 4;
                ldm_x4(a, addr);
            }
#pragma unroll
            for (int nbp = 0; nbp < 8; nbp++) {
                const int row_j = ks * 16 + (m_id & 1) * 8 + lr;
                const uint32_t addr =
                    sb + (uint32_t)(kVOff + row_j * 64 +
                                    (((nbp * 2 + (m_id >> 1)) ^ (row_j & 7)) << 2)) * 4;
                uint32_t b4[4];
                ldm_x4_t(b4, addr);
                mma_f16(oacc[2 * nbp], a, b4);
                mma_f16(oacc[2 * nbp + 1], a, b4 + 2);
            }
        }
    }

    // ---- epilogue: normalize and store ----
    const float inv1 = 1.f / l1;
    const float inv2 = 1.f / l2;
    const int row1 = s * kQLen + q0 + qr0 + g;
    float* o1 = out + (size_t)row1 * kOutCols + h * kHeadDim;
    float* o2 = o1 + (size_t)8 * kOutCols;
#pragma unroll
    for (int nb = 0; nb < 16; nb++) {
        const int cc = nb * 8 + 2 * t;
        float2 w1 = make_float2(oacc[nb][0] * inv1, oacc[nb][1] * inv1);
        float2 w2 = make_float2(oacc[nb][2] * inv2, oacc[nb][3] * inv2);
        *(float2*)(o1 + cc) = w1;
        *(float2*)(o2 + cc) = w2;
    }
}

extern "C" void kernel_launch(void* const* d_in, const int* in_sizes, int n_in,
                              void* d_out, int out_size) {
    const float* q  = (const float*)d_in[0];
    const float* k  = (const float*)d_in[1];
    const float* v  = (const float*)d_in[2];
    const float* kc = (const float*)d_in[3];
    const float* vc = (const float*)d_in[4];
    const int* ctx = (const int*)d_in[6];
    float* out = (float*)d_out;

    const int smem_bytes = kSmemU32 * (int)sizeof(uint32_t);
    cudaFuncSetAttribute(fa_fp16_kernel,
                         cudaFuncAttributeMaxDynamicSharedMemorySize, smem_bytes);
    dim3 grid(kQLen / BM, kHeads, kNSeqs);
    fa_fp16_kernel<<<grid, kThreads, smem_bytes>>>(q, k, v, kc, vc, ctx, out);
}